// round 12
// baseline (speedup 1.0000x reference)
#include <cuda_runtime.h>

#define N 8192
#define F 128
#define ALPHA 0.2f
#define PRO_BLOCKS 512          // <= guaranteed wave-1 residency (1184 @ 8 CTA/SM)
#define PRO_WARPS (PRO_BLOCKS * 8)

// Allocation-free scratch (zero-initialized at module load)
__device__ float g_si[N];
__device__ float g_sj[N];
__device__ int   g_ready;
__device__ int   g_done;

__global__ __launch_bounds__(256, 8) void gat_kernel(
    const float* __restrict__ vi, const float* __restrict__ vj,
    const float* __restrict__ W,  const float* __restrict__ a,
    const int* __restrict__ adj,  float* __restrict__ out) {
    __shared__ float sWa1[F];
    __shared__ float sWa2[F];
    __shared__ float red[8];
    __shared__ float bcast;

    const int b    = blockIdx.x;
    const int tid  = threadIdx.x;
    const int lane = tid & 31;
    const int wid  = tid >> 5;
    const int row  = b;

    const int4* adj4 = reinterpret_cast<const int4*>(adj + (size_t)row * N);

    // Prefetch this row's adj toward L2 first (hides under prologue/spin).
    if (b < 2368) {
#pragma unroll
        for (int it = 0; it < 8; ++it)
            asm volatile("prefetch.global.L2 [%0];" :: "l"(adj4 + tid + it * 256));
    }

    // ---------- Prologue (blocks 0..511): Wa + si/sj ----------
    if (b < PRO_BLOCKS) {
        // Wa redundant per block, coalesced: warp wid handles rows wid*16..+15
        const float4 a1v = reinterpret_cast<const float4*>(a)[lane];
        const float4 a2v = reinterpret_cast<const float4*>(a)[32 + lane];
#pragma unroll
        for (int r = 0; r < 16; ++r) {
            const int wr = wid * 16 + r;
            float4 wv = reinterpret_cast<const float4*>(W + wr * F)[lane];
            float s1 = fmaf(wv.x, a1v.x, fmaf(wv.y, a1v.y, fmaf(wv.z, a1v.z, wv.w * a1v.w)));
            float s2 = fmaf(wv.x, a2v.x, fmaf(wv.y, a2v.y, fmaf(wv.z, a2v.z, wv.w * a2v.w)));
#pragma unroll
            for (int o = 16; o > 0; o >>= 1) {
                s1 += __shfl_xor_sync(0xffffffffu, s1, o);
                s2 += __shfl_xor_sync(0xffffffffu, s2, o);
            }
            if (lane == 0) { sWa1[wr] = s1; sWa2[wr] = s2; }
        }
        __syncthreads();

        const float4 a1 = reinterpret_cast<const float4*>(sWa1)[lane];
        const float4 a2 = reinterpret_cast<const float4*>(sWa2)[lane];
#pragma unroll
        for (int rep = 0; rep < 2; ++rep) {
            const int prow = b * 8 + wid + rep * PRO_WARPS;
            float4 x1 = reinterpret_cast<const float4*>(vi + (size_t)prow * F)[lane];
            float4 x2 = reinterpret_cast<const float4*>(vj + (size_t)prow * F)[lane];
            float s1 = fmaf(x1.x, a1.x, fmaf(x1.y, a1.y, fmaf(x1.z, a1.z, x1.w * a1.w)));
            float s2 = fmaf(x2.x, a2.x, fmaf(x2.y, a2.y, fmaf(x2.z, a2.z, x2.w * a2.w)));
#pragma unroll
            for (int o = 16; o > 0; o >>= 1) {
                s1 += __shfl_down_sync(0xffffffffu, s1, o);
                s2 += __shfl_down_sync(0xffffffffu, s2, o);
            }
            if (lane == 0) { g_si[prow] = s1; g_sj[prow] = s2; }
        }
        __syncthreads();
        if (tid == 0) {
            __threadfence();                 // release: publish si/sj
            atomicAdd(&g_ready, 1);
        }
    }

    // ---------- Acquire: wait until all prologue blocks published ----------
    if (tid == 0) {
        while (*(volatile int*)&g_ready < PRO_BLOCKS) __nanosleep(128);
        __threadfence();                     // acquire: invalidate L1
    }
    __syncthreads();

    // ---------- Frozen softmax body (R6/R7/R9 best: 85.9-87.3us) ----------
    const float si = g_si[row];
    const float4* sj4 = reinterpret_cast<const float4*>(g_sj);
    float4* out4 = reinterpret_cast<float4*>(out + (size_t)row * N);

    float4 preg[8];
    float lsum = 0.f;
#pragma unroll
    for (int it = 0; it < 8; ++it) {
        const int j = tid + it * 256;
        int4   av = __ldcs(&adj4[j]);
        float4 sj = sj4[j];
        float4 p;
        float t;
        t = si + sj.x; t = t > 0.f ? t : ALPHA * t; p.x = av.x > 0 ? __expf(t) : 0.f;
        t = si + sj.y; t = t > 0.f ? t : ALPHA * t; p.y = av.y > 0 ? __expf(t) : 0.f;
        t = si + sj.z; t = t > 0.f ? t : ALPHA * t; p.z = av.z > 0 ? __expf(t) : 0.f;
        t = si + sj.w; t = t > 0.f ? t : ALPHA * t; p.w = av.w > 0 ? __expf(t) : 0.f;
        preg[it] = p;
        lsum += (p.x + p.y) + (p.z + p.w);
    }
#pragma unroll
    for (int o = 16; o > 0; o >>= 1)
        lsum += __shfl_xor_sync(0xffffffffu, lsum, o);
    if (lane == 0) red[wid] = lsum;
    __syncthreads();
    if (wid == 0) {
        float s = (lane < 8) ? red[lane] : 0.f;
#pragma unroll
        for (int o = 4; o > 0; o >>= 1)
            s += __shfl_xor_sync(0xffffffffu, s, o);
        if (lane == 0) bcast = 1.0f / s;
    }
    __syncthreads();
    const float inv = bcast;

#pragma unroll
    for (int it = 0; it < 8; ++it) {
        float4 p = preg[it];
        p.x *= inv; p.y *= inv; p.z *= inv; p.w *= inv;
        __stcs(&out4[tid + it * 256], p);
    }

    // ---------- Epilogue: last block resets counters for graph replay ----------
    if (tid == 0) {
        int v = atomicAdd(&g_done, 1);
        if (v == gridDim.x - 1) {
            g_ready = 0;
            g_done  = 0;
            __threadfence();
        }
    }
}

extern "C" void kernel_launch(void* const* d_in, const int* in_sizes, int n_in,
                              void* d_out, int out_size) {
    const float* v_i = (const float*)d_in[0];
    const float* v_j = (const float*)d_in[1];
    const int*   adj = (const int*)d_in[2];
    const float* W   = (const float*)d_in[3];
    const float* a   = (const float*)d_in[4];
    float* out = (float*)d_out;

    gat_kernel<<<N, 256>>>(v_i, v_j, W, a, adj, out);
}

// round 13
// speedup vs baseline: 1.1746x; 1.1746x over previous
#include <cuda_runtime.h>

#define N 8192
#define F 128
#define ALPHA 0.2f
#define PRO_BLOCKS 148
#define PRO_WARPS (PRO_BLOCKS * 32)

// Allocation-free scratch
__device__ float g_si[N];
__device__ float g_sj[N];

// Prologue: one wave (148 x 1024).
// vi/vj row loads issued FIRST (latency hidden under Wa compute);
// 'a' loaded directly (coalesced, L1-broadcast); Wa via shared once.
__global__ __launch_bounds__(1024) void prologue_kernel(
    const float* __restrict__ vi, const float* __restrict__ vj,
    const float* __restrict__ W, const float* __restrict__ a) {
#if __CUDA_ARCH__ >= 900
    cudaTriggerProgrammaticLaunchCompletion();
#endif
    __shared__ float sWa1[F];
    __shared__ float sWa2[F];

    const int tid = threadIdx.x;
    const int lane = tid & 31;
    const int wid = tid >> 5;

    // Early: issue this warp's vi/vj loads (independent of Wa)
    const int row0 = blockIdx.x * 32 + wid;            // < 4736, always valid
    const int row1 = row0 + PRO_WARPS;                 // may exceed N
    const bool has1 = (row1 < N);
    float4 x1a = reinterpret_cast<const float4*>(vi + (size_t)row0 * F)[lane];
    float4 x2a = reinterpret_cast<const float4*>(vj + (size_t)row0 * F)[lane];
    float4 x1b = make_float4(0.f, 0.f, 0.f, 0.f);
    float4 x2b = make_float4(0.f, 0.f, 0.f, 0.f);
    if (has1) {
        x1b = reinterpret_cast<const float4*>(vi + (size_t)row1 * F)[lane];
        x2b = reinterpret_cast<const float4*>(vj + (size_t)row1 * F)[lane];
    }

    // 'a' directly from global: a1 = a[0:128], a2 = a[128:256]
    const float4 a1v = reinterpret_cast<const float4*>(a)[lane];
    const float4 a2v = reinterpret_cast<const float4*>(a)[32 + lane];

    // Phase 1: warp w computes Wa rows w*4 .. w*4+3 (coalesced float4)
#pragma unroll
    for (int r = 0; r < 4; ++r) {
        const int row = wid * 4 + r;
        float4 wv = reinterpret_cast<const float4*>(W + row * F)[lane];
        float s1 = fmaf(wv.x, a1v.x, fmaf(wv.y, a1v.y, fmaf(wv.z, a1v.z, wv.w * a1v.w)));
        float s2 = fmaf(wv.x, a2v.x, fmaf(wv.y, a2v.y, fmaf(wv.z, a2v.z, wv.w * a2v.w)));
#pragma unroll
        for (int o = 16; o > 0; o >>= 1) {
            s1 += __shfl_xor_sync(0xffffffffu, s1, o);
            s2 += __shfl_xor_sync(0xffffffffu, s2, o);
        }
        if (lane == 0) { sWa1[row] = s1; sWa2[row] = s2; }
    }
    __syncthreads();

    // Phase 2: consume preloaded rows
    const float4 a1 = reinterpret_cast<const float4*>(sWa1)[lane];
    const float4 a2 = reinterpret_cast<const float4*>(sWa2)[lane];
    {
        float s1 = fmaf(x1a.x, a1.x, fmaf(x1a.y, a1.y, fmaf(x1a.z, a1.z, x1a.w * a1.w)));
        float s2 = fmaf(x2a.x, a2.x, fmaf(x2a.y, a2.y, fmaf(x2a.z, a2.z, x2a.w * a2.w)));
#pragma unroll
        for (int o = 16; o > 0; o >>= 1) {
            s1 += __shfl_down_sync(0xffffffffu, s1, o);
            s2 += __shfl_down_sync(0xffffffffu, s2, o);
        }
        if (lane == 0) { g_si[row0] = s1; g_sj[row0] = s2; }
    }
    if (has1) {
        float s1 = fmaf(x1b.x, a1.x, fmaf(x1b.y, a1.y, fmaf(x1b.z, a1.z, x1b.w * a1.w)));
        float s2 = fmaf(x2b.x, a2.x, fmaf(x2b.y, a2.y, fmaf(x2b.z, a2.z, x2b.w * a2.w)));
#pragma unroll
        for (int o = 16; o > 0; o >>= 1) {
            s1 += __shfl_down_sync(0xffffffffu, s1, o);
            s2 += __shfl_down_sync(0xffffffffu, s2, o);
        }
        if (lane == 0) { g_si[row1] = s1; g_sj[row1] = s2; }
    }
}

// Softmax: FROZEN body (best measured 85.9us). One block per row,
// register-staged p, no max pass, two-barrier bcast reduction.
__global__ __launch_bounds__(256, 8) void softmax_row_kernel(
    const int* __restrict__ adj, float* __restrict__ out) {
    __shared__ float red[8];
    __shared__ float bcast;

    const int row = blockIdx.x;
    const int tid = threadIdx.x;
    const int lane = tid & 31;
    const int wid = tid >> 5;

    const int4*   adj4 = reinterpret_cast<const int4*>(adj + (size_t)row * N);
    const float4* sj4  = reinterpret_cast<const float4*>(g_sj);
    float4* out4 = reinterpret_cast<float4*>(out + (size_t)row * N);

    if (row < 2368) {
#pragma unroll
        for (int it = 0; it < 8; ++it)
            asm volatile("prefetch.global.L2 [%0];" :: "l"(adj4 + tid + it * 256));
    }
#if __CUDA_ARCH__ >= 900
    cudaGridDependencySynchronize();
#endif

    const float si = g_si[row];
    float4 preg[8];
    float lsum = 0.f;
#pragma unroll
    for (int it = 0; it < 8; ++it) {
        const int j = tid + it * 256;
        int4   av = __ldcs(&adj4[j]);
        float4 sj = sj4[j];
        float4 p;
        float t;
        t = si + sj.x; t = t > 0.f ? t : ALPHA * t; p.x = av.x > 0 ? __expf(t) : 0.f;
        t = si + sj.y; t = t > 0.f ? t : ALPHA * t; p.y = av.y > 0 ? __expf(t) : 0.f;
        t = si + sj.z; t = t > 0.f ? t : ALPHA * t; p.z = av.z > 0 ? __expf(t) : 0.f;
        t = si + sj.w; t = t > 0.f ? t : ALPHA * t; p.w = av.w > 0 ? __expf(t) : 0.f;
        preg[it] = p;
        lsum += (p.x + p.y) + (p.z + p.w);
    }
#pragma unroll
    for (int o = 16; o > 0; o >>= 1)
        lsum += __shfl_xor_sync(0xffffffffu, lsum, o);
    if (lane == 0) red[wid] = lsum;
    __syncthreads();
    if (wid == 0) {
        float s = (lane < 8) ? red[lane] : 0.f;
#pragma unroll
        for (int o = 4; o > 0; o >>= 1)
            s += __shfl_xor_sync(0xffffffffu, s, o);
        if (lane == 0) bcast = 1.0f / s;
    }
    __syncthreads();
    const float inv = bcast;

#pragma unroll
    for (int it = 0; it < 8; ++it) {
        float4 p = preg[it];
        p.x *= inv; p.y *= inv; p.z *= inv; p.w *= inv;
        __stcs(&out4[tid + it * 256], p);
    }
}

extern "C" void kernel_launch(void* const* d_in, const int* in_sizes, int n_in,
                              void* d_out, int out_size) {
    const float* v_i = (const float*)d_in[0];
    const float* v_j = (const float*)d_in[1];
    const int*   adj = (const int*)d_in[2];
    const float* W   = (const float*)d_in[3];
    const float* a   = (const float*)d_in[4];
    float* out = (float*)d_out;

    prologue_kernel<<<PRO_BLOCKS, 1024>>>(v_i, v_j, W, a);

    cudaLaunchConfig_t cfg = {};
    cfg.gridDim = dim3(N, 1, 1);
    cfg.blockDim = dim3(256, 1, 1);
    cfg.dynamicSmemBytes = 0;
    cfg.stream = 0;
    cudaLaunchAttribute attrs[1];
    attrs[0].id = cudaLaunchAttributeProgrammaticStreamSerialization;
    attrs[0].val.programmaticStreamSerializationAllowed = 1;
    cfg.attrs = attrs;
    cfg.numAttrs = 1;
    cudaLaunchKernelEx(&cfg, softmax_row_kernel, adj, out);
}

// round 14
// speedup vs baseline: 1.1775x; 1.0024x over previous
#include <cuda_runtime.h>

#define N 8192
#define F 128
#define ALPHA 0.2f
#define PRO_BLOCKS 148
#define PRO_WARPS (PRO_BLOCKS * 32)

// Allocation-free scratch
__device__ float g_si[N];
__device__ float g_sj[N];

// Prologue: one wave (148 x 1024).
// vi/vj row loads issued FIRST (latency hidden under Wa compute);
// 'a' loaded directly (coalesced, L1-broadcast); Wa via shared once.
__global__ __launch_bounds__(1024) void prologue_kernel(
    const float* __restrict__ vi, const float* __restrict__ vj,
    const float* __restrict__ W, const float* __restrict__ a) {
#if __CUDA_ARCH__ >= 900
    cudaTriggerProgrammaticLaunchCompletion();
#endif
    __shared__ float sWa1[F];
    __shared__ float sWa2[F];

    const int tid = threadIdx.x;
    const int lane = tid & 31;
    const int wid = tid >> 5;

    // Early: issue this warp's vi/vj loads (independent of Wa)
    const int row0 = blockIdx.x * 32 + wid;            // < 4736, always valid
    const int row1 = row0 + PRO_WARPS;                 // may exceed N
    const bool has1 = (row1 < N);
    float4 x1a = reinterpret_cast<const float4*>(vi + (size_t)row0 * F)[lane];
    float4 x2a = reinterpret_cast<const float4*>(vj + (size_t)row0 * F)[lane];
    float4 x1b = make_float4(0.f, 0.f, 0.f, 0.f);
    float4 x2b = make_float4(0.f, 0.f, 0.f, 0.f);
    if (has1) {
        x1b = reinterpret_cast<const float4*>(vi + (size_t)row1 * F)[lane];
        x2b = reinterpret_cast<const float4*>(vj + (size_t)row1 * F)[lane];
    }

    // 'a' directly from global: a1 = a[0:128], a2 = a[128:256]
    const float4 a1v = reinterpret_cast<const float4*>(a)[lane];
    const float4 a2v = reinterpret_cast<const float4*>(a)[32 + lane];

    // Phase 1: warp w computes Wa rows w*4 .. w*4+3 (coalesced float4)
#pragma unroll
    for (int r = 0; r < 4; ++r) {
        const int row = wid * 4 + r;
        float4 wv = reinterpret_cast<const float4*>(W + row * F)[lane];
        float s1 = fmaf(wv.x, a1v.x, fmaf(wv.y, a1v.y, fmaf(wv.z, a1v.z, wv.w * a1v.w)));
        float s2 = fmaf(wv.x, a2v.x, fmaf(wv.y, a2v.y, fmaf(wv.z, a2v.z, wv.w * a2v.w)));
#pragma unroll
        for (int o = 16; o > 0; o >>= 1) {
            s1 += __shfl_xor_sync(0xffffffffu, s1, o);
            s2 += __shfl_xor_sync(0xffffffffu, s2, o);
        }
        if (lane == 0) { sWa1[row] = s1; sWa2[row] = s2; }
    }
    __syncthreads();

    // Phase 2: consume preloaded rows
    const float4 a1 = reinterpret_cast<const float4*>(sWa1)[lane];
    const float4 a2 = reinterpret_cast<const float4*>(sWa2)[lane];
    {
        float s1 = fmaf(x1a.x, a1.x, fmaf(x1a.y, a1.y, fmaf(x1a.z, a1.z, x1a.w * a1.w)));
        float s2 = fmaf(x2a.x, a2.x, fmaf(x2a.y, a2.y, fmaf(x2a.z, a2.z, x2a.w * a2.w)));
#pragma unroll
        for (int o = 16; o > 0; o >>= 1) {
            s1 += __shfl_down_sync(0xffffffffu, s1, o);
            s2 += __shfl_down_sync(0xffffffffu, s2, o);
        }
        if (lane == 0) { g_si[row0] = s1; g_sj[row0] = s2; }
    }
    if (has1) {
        float s1 = fmaf(x1b.x, a1.x, fmaf(x1b.y, a1.y, fmaf(x1b.z, a1.z, x1b.w * a1.w)));
        float s2 = fmaf(x2b.x, a2.x, fmaf(x2b.y, a2.y, fmaf(x2b.z, a2.z, x2b.w * a2.w)));
#pragma unroll
        for (int o = 16; o > 0; o >>= 1) {
            s1 += __shfl_down_sync(0xffffffffu, s1, o);
            s2 += __shfl_down_sync(0xffffffffu, s2, o);
        }
        if (lane == 0) { g_si[row1] = s1; g_sj[row1] = s2; }
    }
}

// Softmax: FROZEN body (best measured 85.9us). One block per row,
// register-staged p, no max pass, two-barrier bcast reduction.
__global__ __launch_bounds__(256, 8) void softmax_row_kernel(
    const int* __restrict__ adj, float* __restrict__ out) {
    __shared__ float red[8];
    __shared__ float bcast;

    const int row = blockIdx.x;
    const int tid = threadIdx.x;
    const int lane = tid & 31;
    const int wid = tid >> 5;

    const int4*   adj4 = reinterpret_cast<const int4*>(adj + (size_t)row * N);
    const float4* sj4  = reinterpret_cast<const float4*>(g_sj);
    float4* out4 = reinterpret_cast<float4*>(out + (size_t)row * N);

    if (row < 2368) {
#pragma unroll
        for (int it = 0; it < 8; ++it)
            asm volatile("prefetch.global.L2 [%0];" :: "l"(adj4 + tid + it * 256));
    }
#if __CUDA_ARCH__ >= 900
    cudaGridDependencySynchronize();
#endif

    const float si = g_si[row];
    float4 preg[8];
    float lsum = 0.f;
#pragma unroll
    for (int it = 0; it < 8; ++it) {
        const int j = tid + it * 256;
        int4   av = __ldcs(&adj4[j]);
        float4 sj = sj4[j];
        float4 p;
        float t;
        t = si + sj.x; t = t > 0.f ? t : ALPHA * t; p.x = av.x > 0 ? __expf(t) : 0.f;
        t = si + sj.y; t = t > 0.f ? t : ALPHA * t; p.y = av.y > 0 ? __expf(t) : 0.f;
        t = si + sj.z; t = t > 0.f ? t : ALPHA * t; p.z = av.z > 0 ? __expf(t) : 0.f;
        t = si + sj.w; t = t > 0.f ? t : ALPHA * t; p.w = av.w > 0 ? __expf(t) : 0.f;
        preg[it] = p;
        lsum += (p.x + p.y) + (p.z + p.w);
    }
#pragma unroll
    for (int o = 16; o > 0; o >>= 1)
        lsum += __shfl_xor_sync(0xffffffffu, lsum, o);
    if (lane == 0) red[wid] = lsum;
    __syncthreads();
    if (wid == 0) {
        float s = (lane < 8) ? red[lane] : 0.f;
#pragma unroll
        for (int o = 4; o > 0; o >>= 1)
            s += __shfl_xor_sync(0xffffffffu, s, o);
        if (lane == 0) bcast = 1.0f / s;
    }
    __syncthreads();
    const float inv = bcast;

#pragma unroll
    for (int it = 0; it < 8; ++it) {
        float4 p = preg[it];
        p.x *= inv; p.y *= inv; p.z *= inv; p.w *= inv;
        __stcs(&out4[tid + it * 256], p);
    }
}

extern "C" void kernel_launch(void* const* d_in, const int* in_sizes, int n_in,
                              void* d_out, int out_size) {
    const float* v_i = (const float*)d_in[0];
    const float* v_j = (const float*)d_in[1];
    const int*   adj = (const int*)d_in[2];
    const float* W   = (const float*)d_in[3];
    const float* a   = (const float*)d_in[4];
    float* out = (float*)d_out;

    prologue_kernel<<<PRO_BLOCKS, 1024>>>(v_i, v_j, W, a);

    cudaLaunchConfig_t cfg = {};
    cfg.gridDim = dim3(N, 1, 1);
    cfg.blockDim = dim3(256, 1, 1);
    cfg.dynamicSmemBytes = 0;
    cfg.stream = 0;
    cudaLaunchAttribute attrs[1];
    attrs[0].id = cudaLaunchAttributeProgrammaticStreamSerialization;
    attrs[0].val.programmaticStreamSerializationAllowed = 1;
    cfg.attrs = attrs;
    cfg.numAttrs = 1;
    cudaLaunchKernelEx(&cfg, softmax_row_kernel, adj, out);
}